// round 1
// baseline (speedup 1.0000x reference)
#include <cuda_runtime.h>
#include <cuda_bf16.h>
#include <math.h>
#include <stdint.h>

// ---------------------------------------------------------------------------
// Problem constants (shapes are fixed by the reference setup)
// ---------------------------------------------------------------------------
#define kC    384
#define kB    2
#define kDHW  50176            // 16*56*56
#define kN    100352           // kB*kDHW tokens; == 784*128
#define k3C   1152
#define kHid  1536

// ---------------------------------------------------------------------------
// Scratch (allocation-free rule: __device__ globals)
// ---------------------------------------------------------------------------
__device__ __nv_bfloat16 g_z1 [(size_t)kN * kC];     // LN(xt)*ln1_g+ln1_b
__device__ __nv_bfloat16 g_z2 [(size_t)kN * kC];     // LN(xt)*ln2_g+ln2_b
__device__ __nv_bfloat16 g_qkv[(size_t)kN * k3C];
__device__ __nv_bfloat16 g_a  [(size_t)kN * kC];     // attention out (pre-gamma1)
__device__ __nv_bfloat16 g_u  [(size_t)kN * kC];
__device__ __nv_bfloat16 g_g2u[(size_t)kN * kC];     // aff2_g*u+aff2_b
__device__ __nv_bfloat16 g_h  [(size_t)kN * kHid];
__device__ __nv_bfloat16 g_w  [(size_t)kN * kC];     // affout(v)
__device__ __nv_bfloat16 g_m  [(size_t)kN * kC];     // mlp out (pre-gamma2)

__device__ __nv_bfloat16 g_wq [(size_t)k3C * kC];
__device__ __nv_bfloat16 g_we [(size_t)kC  * kC];
__device__ __nv_bfloat16 g_w1 [(size_t)kHid* kC];
__device__ __nv_bfloat16 g_w2 [(size_t)kC  * kHid];
__device__ __nv_bfloat16 g_wh [(size_t)kC  * kC];

// ---------------------------------------------------------------------------
// Small helpers
// ---------------------------------------------------------------------------
__device__ __forceinline__ void cp_async16(void* smem_ptr, const void* gmem_ptr) {
    uint32_t s = (uint32_t)__cvta_generic_to_shared(smem_ptr);
    asm volatile("cp.async.cg.shared.global [%0], [%1], 16;\n" :: "r"(s), "l"(gmem_ptr));
}
__device__ __forceinline__ void cp_commit() { asm volatile("cp.async.commit_group;\n"); }
template <int NW> __device__ __forceinline__ void cp_wait() {
    asm volatile("cp.async.wait_group %0;\n" :: "n"(NW));
}

__device__ __forceinline__ void mma16816(float* c, const uint32_t* a, const uint32_t* b) {
    asm volatile(
        "mma.sync.aligned.m16n8k16.row.col.f32.bf16.bf16.f32 "
        "{%0,%1,%2,%3}, {%4,%5,%6,%7}, {%8,%9}, {%0,%1,%2,%3};\n"
        : "+f"(c[0]), "+f"(c[1]), "+f"(c[2]), "+f"(c[3])
        : "r"(a[0]), "r"(a[1]), "r"(a[2]), "r"(a[3]), "r"(b[0]), "r"(b[1]));
}

// ---------------------------------------------------------------------------
// K0: fp32 -> bf16 weight convert
// ---------------------------------------------------------------------------
__global__ void cvt_kernel(const float* __restrict__ src, __nv_bfloat16* __restrict__ dst, int n) {
    int i = blockIdx.x * blockDim.x + threadIdx.x;
    if (i < n) dst[i] = __float2bfloat16(src[i]);
}

// ---------------------------------------------------------------------------
// K1: fused (B,C,DHW) -> (N,C) transpose + LayerNorm, two affine outputs
// block = 64 consecutive tokens (contiguous in DHW), dynamic smem
// ---------------------------------------------------------------------------
#define LN_SMEM ((384*65 + 128) * 4)
__global__ void __launch_bounds__(256) ln_transpose_kernel(
    const float* __restrict__ x,
    const float* __restrict__ g1, const float* __restrict__ b1,
    const float* __restrict__ g2, const float* __restrict__ b2,
    __nv_bfloat16* __restrict__ z1, __nv_bfloat16* __restrict__ z2)
{
    extern __shared__ float sx[];            // [384][65] + mu[64] + rstd[64]
    const int tid = threadIdx.x;
    const int blk = blockIdx.x;
    const int b   = blk / (kDHW / 64);
    const int nl0 = (blk % (kDHW / 64)) * 64;
    const float* xb = x + (size_t)b * kC * kDHW + nl0;

    // load 384 channels x 64 tokens, coalesced along DHW
    for (int idx = tid; idx < 384 * 16; idx += 256) {
        int c = idx >> 4, q = idx & 15;
        float4 v = *(const float4*)(xb + (size_t)c * kDHW + q * 4);
        float* dst = sx + c * 65 + q * 4;
        dst[0] = v.x; dst[1] = v.y; dst[2] = v.z; dst[3] = v.w;
    }
    __syncthreads();

    float* smu = sx + 384 * 65;
    float* srs = smu + 64;
    const int wid = tid >> 5, lane = tid & 31;
    for (int t = wid; t < 64; t += 8) {
        float s = 0.f, ss = 0.f;
        #pragma unroll
        for (int i = 0; i < 12; i++) {
            float v = sx[(lane + 32 * i) * 65 + t];
            s += v; ss += v * v;
        }
        #pragma unroll
        for (int o = 16; o > 0; o >>= 1) {
            s  += __shfl_xor_sync(0xffffffffu, s,  o);
            ss += __shfl_xor_sync(0xffffffffu, ss, o);
        }
        if (lane == 0) {
            float mu = s * (1.f / 384.f);
            float var = ss * (1.f / 384.f) - mu * mu;
            smu[t] = mu;
            srs[t] = rsqrtf(var + 1e-5f);
        }
    }
    __syncthreads();

    for (int idx = tid; idx < 64 * 384; idx += 256) {
        int t = idx / 384, c = idx % 384;
        float v = (sx[c * 65 + t] - smu[t]) * srs[t];
        size_t o = (size_t)(b * kDHW + nl0 + t) * kC + c;
        z1[o] = __float2bfloat16(v * g1[c] + b1[c]);
        z2[o] = __float2bfloat16(v * g2[c] + b2[c]);
    }
}

// ---------------------------------------------------------------------------
// Epilogue functors for the GEMM
// ---------------------------------------------------------------------------
struct EpiBias {        // y + bias -> bf16
    const float* bias; __nv_bfloat16* out; int ldo;
    __device__ __forceinline__ void operator()(int r, int c, float v0, float v1) const {
        size_t o = (size_t)r * ldo + c;
        *(__nv_bfloat162*)(out + o) = __floats2bfloat162_rn(v0 + bias[c], v1 + bias[c + 1]);
    }
};
struct EpiEmbed {       // t = y+b; u = t + ls_a*(tw*(a1g*t+a1b)+tb); also aff2(u)
    const float *bias, *ls_a, *a1g, *a1b, *tok_w, *tok_b, *a2g, *a2b;
    __nv_bfloat16 *u_out, *g2u_out;
    __device__ __forceinline__ void operator()(int r, int c, float v0, float v1) const {
        float tw = *tok_w, tb = *tok_b;
        float t0 = v0 + bias[c], t1 = v1 + bias[c + 1];
        float u0 = t0 + ls_a[c]     * (tw * (a1g[c]     * t0 + a1b[c])     + tb);
        float u1 = t1 + ls_a[c + 1] * (tw * (a1g[c + 1] * t1 + a1b[c + 1]) + tb);
        size_t o = (size_t)r * kC + c;
        *(__nv_bfloat162*)(u_out + o)   = __floats2bfloat162_rn(u0, u1);
        *(__nv_bfloat162*)(g2u_out + o) = __floats2bfloat162_rn(a2g[c] * u0 + a2b[c],
                                                                a2g[c + 1] * u1 + a2b[c + 1]);
    }
};
struct EpiGelu {        // h = gelu_exact(y + bias)
    const float* bias; __nv_bfloat16* out;
    __device__ __forceinline__ void operator()(int r, int c, float v0, float v1) const {
        float x0 = v0 + bias[c], x1 = v1 + bias[c + 1];
        float h0 = 0.5f * x0 * (1.f + erff(x0 * 0.70710678118654752f));
        float h1 = 0.5f * x1 * (1.f + erff(x1 * 0.70710678118654752f));
        size_t o = (size_t)r * kHid + c;
        *(__nv_bfloat162*)(out + o) = __floats2bfloat162_rn(h0, h1);
    }
};
struct EpiFc2 {         // v = u + ls_b*(y+b); w = affout_g*v + affout_b
    const float *bias, *ls_b, *aog, *aob;
    const __nv_bfloat16* u; __nv_bfloat16* out;
    __device__ __forceinline__ void operator()(int r, int c, float v0, float v1) const {
        size_t o = (size_t)r * kC + c;
        __nv_bfloat162 up = *(const __nv_bfloat162*)(u + o);
        float vv0 = __bfloat162float(up.x) + ls_b[c]     * (v0 + bias[c]);
        float vv1 = __bfloat162float(up.y) + ls_b[c + 1] * (v1 + bias[c + 1]);
        *(__nv_bfloat162*)(out + o) = __floats2bfloat162_rn(aog[c] * vv0 + aob[c],
                                                            aog[c + 1] * vv1 + aob[c + 1]);
    }
};

// ---------------------------------------------------------------------------
// GEMM: Y[M,N] = A[M,K] @ B[N,K]^T, bf16 in, fp32 accum, fused epilogue
// 128x128x32 tile, 8 warps (2x4), mma.sync m16n8k16, cp.async double buffer
// Requires: M%128==0, N%128==0, K%32==0 (true for all 5 GEMMs here)
// ---------------------------------------------------------------------------
template <class Epi>
__global__ void __launch_bounds__(256) gemm_kernel(
    const __nv_bfloat16* __restrict__ A,
    const __nv_bfloat16* __restrict__ B,
    int M, int N, int K, Epi epi)
{
    constexpr int BM = 128, BN = 128, BK = 32, LD = 40;   // pad 8 -> conflict-free
    __shared__ alignas(16) __nv_bfloat16 sA[2][BM * LD];
    __shared__ alignas(16) __nv_bfloat16 sB[2][BN * LD];

    const int tid = threadIdx.x;
    const int wid = tid >> 5, lane = tid & 31;
    const int wm = wid >> 2, wn = wid & 3;        // 2 x 4 warp grid
    const int gid = lane >> 2, tig = lane & 3;
    const int m0 = blockIdx.y * BM, n0 = blockIdx.x * BN;

    const __nv_bfloat16* Ag = A + (size_t)m0 * K;
    const __nv_bfloat16* Bg = B + (size_t)n0 * K;

    float acc[4][4][4];
    #pragma unroll
    for (int i = 0; i < 4; i++)
        #pragma unroll
        for (int j = 0; j < 4; j++)
            #pragma unroll
            for (int q = 0; q < 4; q++) acc[i][j][q] = 0.f;

    auto load_stage = [&](int kt, int buf) {
        const int k0 = kt * BK;
        #pragma unroll
        for (int r = 0; r < 2; r++) {
            int idx = tid + r * 256;
            int row = idx >> 2, q = idx & 3;
            cp_async16(&sA[buf][row * LD + q * 8], Ag + (size_t)row * K + k0 + q * 8);
            cp_async16(&sB[buf][row * LD + q * 8], Bg + (size_t)row * K + k0 + q * 8);
        }
    };

    load_stage(0, 0); cp_commit();
    const int KT = K / BK;
    for (int kt = 0; kt < KT; ++kt) {
        const int buf = kt & 1;
        if (kt + 1 < KT) { load_stage(kt + 1, buf ^ 1); cp_commit(); cp_wait<1>(); }
        else            { cp_wait<0>(); }
        __syncthreads();

        #pragma unroll
        for (int kk = 0; kk < 2; ++kk) {
            const int kb = kk * 16;
            uint32_t afr[4][4], bfr[4][2];
            #pragma unroll
            for (int mi = 0; mi < 4; mi++) {
                int row = wm * 64 + mi * 16 + gid;
                const __nv_bfloat16* p  = &sA[buf][row * LD + kb + tig * 2];
                const __nv_bfloat16* p2 = p + 8 * LD;
                afr[mi][0] = *(const uint32_t*)p;
                afr[mi][1] = *(const uint32_t*)p2;
                afr[mi][2] = *(const uint32_t*)(p + 8);
                afr[mi][3] = *(const uint32_t*)(p2 + 8);
            }
            #pragma unroll
            for (int ni = 0; ni < 4; ni++) {
                int col = wn * 32 + ni * 8 + gid;
                const __nv_bfloat16* p = &sB[buf][col * LD + kb + tig * 2];
                bfr[ni][0] = *(const uint32_t*)p;
                bfr[ni][1] = *(const uint32_t*)(p + 8);
            }
            #pragma unroll
            for (int mi = 0; mi < 4; mi++)
                #pragma unroll
                for (int ni = 0; ni < 4; ni++)
                    mma16816(acc[mi][ni], afr[mi], bfr[ni]);
        }
        __syncthreads();
    }

    #pragma unroll
    for (int mi = 0; mi < 4; mi++) {
        int row = m0 + wm * 64 + mi * 16 + gid;
        #pragma unroll
        for (int ni = 0; ni < 4; ni++) {
            int col = n0 + wn * 32 + ni * 8 + tig * 2;
            epi(row,     col, acc[mi][ni][0], acc[mi][ni][1]);
            epi(row + 8, col, acc[mi][ni][2], acc[mi][ni][3]);
        }
    }
}

// ---------------------------------------------------------------------------
// K3: per-token 12-head x 12-head attention (one warp per token)
// qkv[n, s*384 + h*32 + d];  out a[n, d*12 + i] = o[n,i,d]
// ---------------------------------------------------------------------------
__global__ void __launch_bounds__(128) attn_kernel(
    const __nv_bfloat16* __restrict__ qkv, __nv_bfloat16* __restrict__ a)
{
    __shared__ float s[4][3 * 396 + 144];        // per warp: q,k,v [12][33] + scores[144]
    const int wid = threadIdx.x >> 5, lane = threadIdx.x & 31;
    const int n = blockIdx.x * 4 + wid;

    float* sq = s[wid];
    float* sk = sq + 396;
    float* sv = sk + 396;
    float* sc = sv + 396;

    const __nv_bfloat16* src = qkv + (size_t)n * k3C;
    for (int i = lane; i < 576; i += 32) {
        __nv_bfloat162 v = *(const __nv_bfloat162*)(src + 2 * i);
        int e = 2 * i;
        int sec = e / 384, rr = (e % 384) / 32, d = e % 32;
        float* dst = sq + sec * 396 + rr * 33 + d;
        dst[0] = __bfloat162float(v.x);
        dst[1] = __bfloat162float(v.y);
    }
    __syncwarp();

    const float scale = 0.17677669529663687f;    // 32^-0.5
    for (int p = lane; p < 144; p += 32) {
        int i = p / 12, j = p % 12;
        float acc = 0.f;
        #pragma unroll
        for (int d = 0; d < 32; d++) acc += sq[i * 33 + d] * sk[j * 33 + d];
        sc[p] = acc * scale;
    }
    __syncwarp();

    if (lane < 12) {
        float mx = -1e30f;
        #pragma unroll
        for (int j = 0; j < 12; j++) mx = fmaxf(mx, sc[lane * 12 + j]);
        float e[12], sum = 0.f;
        #pragma unroll
        for (int j = 0; j < 12; j++) { e[j] = expf(sc[lane * 12 + j] - mx); sum += e[j]; }
        float inv = 1.f / sum;
        #pragma unroll
        for (int j = 0; j < 12; j++) sc[lane * 12 + j] = e[j] * inv;
    }
    __syncwarp();

    const int d = lane;
    __nv_bfloat16* dst = a + (size_t)n * kC + d * 12;
    #pragma unroll
    for (int i = 0; i < 12; i++) {
        float acc = 0.f;
        #pragma unroll
        for (int j = 0; j < 12; j++) acc += sc[i * 12 + j] * sv[j * 33 + d];
        dst[i] = __float2bfloat16(acc);
    }
}

// ---------------------------------------------------------------------------
// K8: out[b,c,nl] = x[b,c,nl] + gamma1[c]*a[n,c] + gamma2[c]*m[n,c]
// smem transpose of a,m tiles (64 tokens x 384 ch), coalesced both ways
// ---------------------------------------------------------------------------
#define OUT_SMEM (2 * 64 * 386 * 2)
__global__ void __launch_bounds__(256) out_kernel(
    const float* __restrict__ x,
    const __nv_bfloat16* __restrict__ a, const __nv_bfloat16* __restrict__ m,
    const float* __restrict__ gamma1, const float* __restrict__ gamma2,
    float* __restrict__ out)
{
    extern __shared__ __nv_bfloat16 sh[];
    __nv_bfloat16* sa = sh;                 // [64][386]
    __nv_bfloat16* sm = sh + 64 * 386;
    const int tid = threadIdx.x;
    const int blk = blockIdx.x;
    const int b   = blk / (kDHW / 64);
    const int nl0 = (blk % (kDHW / 64)) * 64;
    const size_t n0 = (size_t)b * kDHW + nl0;

    for (int idx = tid; idx < 64 * 192; idx += 256) {
        int t = idx / 192, cc = idx % 192;
        __nv_bfloat162 va = *(const __nv_bfloat162*)(a + (n0 + t) * kC + cc * 2);
        __nv_bfloat162 vm = *(const __nv_bfloat162*)(m + (n0 + t) * kC + cc * 2);
        sa[t * 386 + cc * 2]     = va.x;
        sa[t * 386 + cc * 2 + 1] = va.y;
        sm[t * 386 + cc * 2]     = vm.x;
        sm[t * 386 + cc * 2 + 1] = vm.y;
    }
    __syncthreads();

    const int tok  = tid & 63;
    const int csub = tid >> 6;              // 0..3
    for (int c = csub; c < kC; c += 4) {
        float av = __bfloat162float(sa[tok * 386 + c]);
        float mv = __bfloat162float(sm[tok * 386 + c]);
        size_t off = (size_t)b * kC * kDHW + (size_t)c * kDHW + nl0 + tok;
        out[off] = x[off] + gamma1[c] * av + gamma2[c] * mv;
    }
}

// ---------------------------------------------------------------------------
// Host launch
// ---------------------------------------------------------------------------
extern "C" void kernel_launch(void* const* d_in, const int* in_sizes, int n_in,
                              void* d_out, int out_size)
{
    (void)in_sizes; (void)n_in; (void)out_size;
    const float* x        = (const float*)d_in[0];
    const float* ln1_g    = (const float*)d_in[1];
    const float* ln1_b    = (const float*)d_in[2];
    const float* ln2_g    = (const float*)d_in[3];
    const float* ln2_b    = (const float*)d_in[4];
    const float* w_qkv    = (const float*)d_in[5];
    const float* b_qkv    = (const float*)d_in[6];
    const float* gamma1   = (const float*)d_in[7];
    const float* gamma2   = (const float*)d_in[8];
    const float* embed_w  = (const float*)d_in[9];
    const float* embed_b  = (const float*)d_in[10];
    const float* aff1_g   = (const float*)d_in[11];
    const float* aff1_b   = (const float*)d_in[12];
    const float* tok_w    = (const float*)d_in[13];
    const float* tok_b    = (const float*)d_in[14];
    const float* ls_a     = (const float*)d_in[15];
    const float* aff2_g   = (const float*)d_in[16];
    const float* aff2_b   = (const float*)d_in[17];
    const float* fc1_w    = (const float*)d_in[18];
    const float* fc1_b    = (const float*)d_in[19];
    const float* fc2_w    = (const float*)d_in[20];
    const float* fc2_b    = (const float*)d_in[21];
    const float* ls_b     = (const float*)d_in[22];
    const float* affout_g = (const float*)d_in[23];
    const float* affout_b = (const float*)d_in[24];
    const float* head_w   = (const float*)d_in[25];
    const float* head_b   = (const float*)d_in[26];
    float* out = (float*)d_out;

    __nv_bfloat16 *z1, *z2, *qkv, *a, *u, *g2u, *h, *wv, *m;
    __nv_bfloat16 *wq, *we, *w1, *w2, *wh;
    cudaGetSymbolAddress((void**)&z1,  g_z1);
    cudaGetSymbolAddress((void**)&z2,  g_z2);
    cudaGetSymbolAddress((void**)&qkv, g_qkv);
    cudaGetSymbolAddress((void**)&a,   g_a);
    cudaGetSymbolAddress((void**)&u,   g_u);
    cudaGetSymbolAddress((void**)&g2u, g_g2u);
    cudaGetSymbolAddress((void**)&h,   g_h);
    cudaGetSymbolAddress((void**)&wv,  g_w);
    cudaGetSymbolAddress((void**)&m,   g_m);
    cudaGetSymbolAddress((void**)&wq,  g_wq);
    cudaGetSymbolAddress((void**)&we,  g_we);
    cudaGetSymbolAddress((void**)&w1,  g_w1);
    cudaGetSymbolAddress((void**)&w2,  g_w2);
    cudaGetSymbolAddress((void**)&wh,  g_wh);

    cudaFuncSetAttribute(ln_transpose_kernel, cudaFuncAttributeMaxDynamicSharedMemorySize, LN_SMEM);
    cudaFuncSetAttribute(out_kernel,          cudaFuncAttributeMaxDynamicSharedMemorySize, OUT_SMEM);

    // K0: weight converts
    cvt_kernel<<<(k3C*kC  + 255)/256, 256>>>(w_qkv,   wq, k3C*kC);
    cvt_kernel<<<(kC*kC   + 255)/256, 256>>>(embed_w, we, kC*kC);
    cvt_kernel<<<(kHid*kC + 255)/256, 256>>>(fc1_w,   w1, kHid*kC);
    cvt_kernel<<<(kC*kHid + 255)/256, 256>>>(fc2_w,   w2, kC*kHid);
    cvt_kernel<<<(kC*kC   + 255)/256, 256>>>(head_w,  wh, kC*kC);

    // K1: transpose + LN (both affines)
    ln_transpose_kernel<<<kN/64, 256, LN_SMEM>>>(x, ln1_g, ln1_b, ln2_g, ln2_b, z1, z2);

    // K2: qkv = z1 @ Wqkv^T + b
    gemm_kernel<<<dim3(k3C/128, kN/128), 256>>>(z1, wq, kN, k3C, kC,
        EpiBias{b_qkv, qkv, k3C});

    // K3: per-token attention
    attn_kernel<<<kN/4, 128>>>(qkv, a);

    // K4: embed + u / aff2(u)
    gemm_kernel<<<dim3(kC/128, kN/128), 256>>>(z2, we, kN, kC, kC,
        EpiEmbed{embed_b, ls_a, aff1_g, aff1_b, tok_w, tok_b, aff2_g, aff2_b, u, g2u});

    // K5: fc1 + gelu
    gemm_kernel<<<dim3(kHid/128, kN/128), 256>>>(g2u, w1, kN, kHid, kC,
        EpiGelu{fc1_b, h});

    // K6: fc2 + residual(u) + affout
    gemm_kernel<<<dim3(kC/128, kN/128), 256>>>(h, w2, kN, kC, kHid,
        EpiFc2{fc2_b, ls_b, affout_g, affout_b, u, wv});

    // K7: head
    gemm_kernel<<<dim3(kC/128, kN/128), 256>>>(wv, wh, kN, kC, kC,
        EpiBias{head_b, m, kC});

    // K8: residual + transpose back to (B,C,D,H,W)
    out_kernel<<<kN/64, 256, OUT_SMEM>>>(x, a, m, gamma1, gamma2, out);
}

// round 2
// speedup vs baseline: 1.1393x; 1.1393x over previous
#include <cuda_runtime.h>
#include <cuda_bf16.h>
#include <math.h>
#include <stdint.h>

// ---------------------------------------------------------------------------
// Problem constants
// ---------------------------------------------------------------------------
#define kC    384
#define kB    2
#define kDHW  50176            // 16*56*56
#define kN    100352           // kB*kDHW tokens == 784*128
#define k3C   1152
#define kHid  1536
#define kQE   1536             // merged qkv(1152)+embed(384) output width

// ---------------------------------------------------------------------------
// Scratch (__device__ globals; allocation-free rule)
// ---------------------------------------------------------------------------
__device__ __nv_bfloat16 g_z  [(size_t)kN * kC];     // LN(xt), no affine
__device__ __nv_bfloat16 g_qkv[(size_t)kN * k3C];
__device__ __nv_bfloat16 g_a  [(size_t)kN * kC];     // attention out (pre-gamma1)
__device__ __nv_bfloat16 g_u  [(size_t)kN * kC];
__device__ __nv_bfloat16 g_h  [(size_t)kN * kHid];
__device__ __nv_bfloat16 g_v  [(size_t)kN * kC];     // u + ls_b*fc2(...)
__device__ __nv_bfloat16 g_m  [(size_t)kN * kC];     // mlp out (pre-gamma2)

__device__ __nv_bfloat16 g_wqe[(size_t)kQE * kC];    // folded [Wqkv∘g1 ; We∘g2]
__device__ __nv_bfloat16 g_w1f[(size_t)kHid* kC];    // fc1_w ∘ aff2_g
__device__ __nv_bfloat16 g_w2 [(size_t)kC  * kHid];  // fc2_w (plain bf16)
__device__ __nv_bfloat16 g_whf[(size_t)kC  * kC];    // head_w ∘ affout_g
__device__ float g_bqe[kQE];
__device__ float g_b1f[kHid];
__device__ float g_bhf[kC];

// ---------------------------------------------------------------------------
// Helpers
// ---------------------------------------------------------------------------
__device__ __forceinline__ void cp_async16(void* smem_ptr, const void* gmem_ptr) {
    uint32_t s = (uint32_t)__cvta_generic_to_shared(smem_ptr);
    asm volatile("cp.async.cg.shared.global [%0], [%1], 16;\n" :: "r"(s), "l"(gmem_ptr));
}
__device__ __forceinline__ void cp_commit() { asm volatile("cp.async.commit_group;\n"); }
template <int NW> __device__ __forceinline__ void cp_wait() {
    asm volatile("cp.async.wait_group %0;\n" :: "n"(NW));
}
__device__ __forceinline__ void ldsm_x4(uint32_t* r, const __nv_bfloat16* p) {
    uint32_t a = (uint32_t)__cvta_generic_to_shared(p);
    asm volatile("ldmatrix.sync.aligned.m8n8.x4.shared.b16 {%0,%1,%2,%3}, [%4];"
        : "=r"(r[0]), "=r"(r[1]), "=r"(r[2]), "=r"(r[3]) : "r"(a));
}
__device__ __forceinline__ void mma16816(float* c, const uint32_t* a, const uint32_t* b) {
    asm volatile(
        "mma.sync.aligned.m16n8k16.row.col.f32.bf16.bf16.f32 "
        "{%0,%1,%2,%3}, {%4,%5,%6,%7}, {%8,%9}, {%0,%1,%2,%3};\n"
        : "+f"(c[0]), "+f"(c[1]), "+f"(c[2]), "+f"(c[3])
        : "r"(a[0]), "r"(a[1]), "r"(a[2]), "r"(a[3]), "r"(b[0]), "r"(b[1]));
}

// ---------------------------------------------------------------------------
// K0a: plain fp32 -> bf16 convert (fc2 weights)
// ---------------------------------------------------------------------------
__global__ void cvt_kernel(const float* __restrict__ src, __nv_bfloat16* __restrict__ dst, int n) {
    int i = blockIdx.x * blockDim.x + threadIdx.x;
    if (i < n) dst[i] = __float2bfloat16(src[i]);
}

// ---------------------------------------------------------------------------
// K0b: fold per-input-channel affine into weights:
//   Wout[r][c] = W[r][c]*g[c] (bf16);  bout[r] = bias[r] + sum_c W[r][c]*b[c]
// one warp per row
// ---------------------------------------------------------------------------
__global__ void __launch_bounds__(128) fold_kernel(
    const float* __restrict__ W, const float* __restrict__ bias,
    const float* __restrict__ g, const float* __restrict__ b,
    __nv_bfloat16* __restrict__ Wout, float* __restrict__ bout,
    int rows, int cols)
{
    int r = blockIdx.x * 4 + (threadIdx.x >> 5);
    int lane = threadIdx.x & 31;
    if (r >= rows) return;
    const float* wr = W + (size_t)r * cols;
    __nv_bfloat16* wo = Wout + (size_t)r * cols;
    float acc = 0.f;
    for (int c = lane; c < cols; c += 32) {
        float w = wr[c];
        acc += w * b[c];
        wo[c] = __float2bfloat16(w * g[c]);
    }
    #pragma unroll
    for (int o = 16; o; o >>= 1) acc += __shfl_xor_sync(0xffffffffu, acc, o);
    if (lane == 0) bout[r] = bias[r] + acc;
}

// ---------------------------------------------------------------------------
// K1: fused (B,C,DHW) -> (N,C) transpose + LayerNorm (no affine; folded)
// ---------------------------------------------------------------------------
#define LN_SMEM ((384*65 + 128) * 4)
__global__ void __launch_bounds__(256) ln_transpose_kernel(
    const float* __restrict__ x, __nv_bfloat16* __restrict__ z)
{
    extern __shared__ float sx[];            // [384][65] + mu[64] + rstd[64]
    const int tid = threadIdx.x;
    const int blk = blockIdx.x;
    const int b   = blk / (kDHW / 64);
    const int nl0 = (blk % (kDHW / 64)) * 64;
    const float* xb = x + (size_t)b * kC * kDHW + nl0;

    for (int idx = tid; idx < 384 * 16; idx += 256) {
        int c = idx >> 4, q = idx & 15;
        float4 v = *(const float4*)(xb + (size_t)c * kDHW + q * 4);
        float* dst = sx + c * 65 + q * 4;
        dst[0] = v.x; dst[1] = v.y; dst[2] = v.z; dst[3] = v.w;
    }
    __syncthreads();

    float* smu = sx + 384 * 65;
    float* srs = smu + 64;
    const int wid = tid >> 5, lane = tid & 31;
    for (int t = wid; t < 64; t += 8) {
        float s = 0.f, ss = 0.f;
        #pragma unroll
        for (int i = 0; i < 12; i++) {
            float v = sx[(lane + 32 * i) * 65 + t];
            s += v; ss += v * v;
        }
        #pragma unroll
        for (int o = 16; o > 0; o >>= 1) {
            s  += __shfl_xor_sync(0xffffffffu, s,  o);
            ss += __shfl_xor_sync(0xffffffffu, ss, o);
        }
        if (lane == 0) {
            float mu = s * (1.f / 384.f);
            float var = ss * (1.f / 384.f) - mu * mu;
            smu[t] = mu;
            srs[t] = rsqrtf(var + 1e-5f);
        }
    }
    __syncthreads();

    for (int idx = tid; idx < 64 * 384; idx += 256) {
        int t = idx / 384, c = idx % 384;
        float v = (sx[c * 65 + t] - smu[t]) * srs[t];
        z[(size_t)(b * kDHW + nl0 + t) * kC + c] = __float2bfloat16(v);
    }
}

// ---------------------------------------------------------------------------
// Epilogues
// ---------------------------------------------------------------------------
struct EpiQkvEmbed {    // cols<1152: qkv = y+bias; else embed->u
    const float* bias;                              // folded, len 1536
    __nv_bfloat16* qkv;
    const float *ls_a, *a1g, *a1b, *tok_w, *tok_b;
    __nv_bfloat16* u_out;
    __device__ __forceinline__ void operator()(int r, int c, float v0, float v1) const {
        float t0 = v0 + bias[c], t1 = v1 + bias[c + 1];
        if (c < k3C) {
            *(__nv_bfloat162*)(qkv + (size_t)r * k3C + c) = __floats2bfloat162_rn(t0, t1);
        } else {
            int cc = c - k3C;
            float tw = *tok_w, tb = *tok_b;
            float u0 = t0 + ls_a[cc]     * (tw * (a1g[cc]     * t0 + a1b[cc])     + tb);
            float u1 = t1 + ls_a[cc + 1] * (tw * (a1g[cc + 1] * t1 + a1b[cc + 1]) + tb);
            *(__nv_bfloat162*)(u_out + (size_t)r * kC + cc) = __floats2bfloat162_rn(u0, u1);
        }
    }
};
struct EpiGelu {        // h = gelu_exact(y + bias)
    const float* bias; __nv_bfloat16* out;
    __device__ __forceinline__ void operator()(int r, int c, float v0, float v1) const {
        float x0 = v0 + bias[c], x1 = v1 + bias[c + 1];
        float h0 = 0.5f * x0 * (1.f + erff(x0 * 0.70710678118654752f));
        float h1 = 0.5f * x1 * (1.f + erff(x1 * 0.70710678118654752f));
        *(__nv_bfloat162*)(out + (size_t)r * kHid + c) = __floats2bfloat162_rn(h0, h1);
    }
};
struct EpiFc2 {         // v = u + ls_b*(y+bias)
    const float *bias, *ls_b;
    const __nv_bfloat16* u; __nv_bfloat16* out;
    __device__ __forceinline__ void operator()(int r, int c, float v0, float v1) const {
        size_t o = (size_t)r * kC + c;
        __nv_bfloat162 up = *(const __nv_bfloat162*)(u + o);
        float vv0 = __bfloat162float(up.x) + ls_b[c]     * (v0 + bias[c]);
        float vv1 = __bfloat162float(up.y) + ls_b[c + 1] * (v1 + bias[c + 1]);
        *(__nv_bfloat162*)(out + o) = __floats2bfloat162_rn(vv0, vv1);
    }
};
struct EpiBias {        // y + bias -> bf16
    const float* bias; __nv_bfloat16* out; int ldo;
    __device__ __forceinline__ void operator()(int r, int c, float v0, float v1) const {
        *(__nv_bfloat162*)(out + (size_t)r * ldo + c) =
            __floats2bfloat162_rn(v0 + bias[c], v1 + bias[c + 1]);
    }
};

// ---------------------------------------------------------------------------
// GEMM: Y[M,N] = A[M,K] @ B[N,K]^T, bf16 in, fp32 accum, fused epilogue
// 128x128x32 tile, 8 warps (2x4), ldmatrix fragments, 4-stage cp.async,
// single __syncthreads per k-iteration.  Requires M%128==N%128==0, K%32==0, K>=96.
// ---------------------------------------------------------------------------
#define GEMM_STAGES 4
#define GEMM_LD     40
#define GEMM_STG    (256 * GEMM_LD)               // elems per stage (A 128 rows + B 128 rows)
#define GEMM_SMEM   (GEMM_STAGES * GEMM_STG * 2)  // bytes

template <class Epi>
__global__ void __launch_bounds__(256, 2) gemm_kernel(
    const __nv_bfloat16* __restrict__ A,
    const __nv_bfloat16* __restrict__ B,
    int M, int N, int K, Epi epi)
{
    constexpr int BM = 128, BK = 32, LD = GEMM_LD;
    extern __shared__ __nv_bfloat16 smem[];

    const int tid = threadIdx.x;
    const int wid = tid >> 5, lane = tid & 31;
    const int wm = wid >> 2, wn = wid & 3;        // 2 x 4 warp grid
    const int m0 = blockIdx.y * 128, n0 = blockIdx.x * 128;

    const __nv_bfloat16* Ag = A + (size_t)m0 * K;
    const __nv_bfloat16* Bg = B + (size_t)n0 * K;

    float acc[4][4][4];
    #pragma unroll
    for (int i = 0; i < 4; i++)
        #pragma unroll
        for (int j = 0; j < 4; j++)
            #pragma unroll
            for (int q = 0; q < 4; q++) acc[i][j][q] = 0.f;

    // per-thread load slots (4 cp.async each for A and B halves)
    const int l_row = tid >> 2, l_q = tid & 3;

    auto load_stage = [&](int kt, int s) {
        const int k0 = kt * BK;
        __nv_bfloat16* sA = smem + (size_t)s * GEMM_STG;
        __nv_bfloat16* sB = sA + BM * LD;
        #pragma unroll
        for (int r = 0; r < 2; r++) {
            int row = l_row + r * 64;
            cp_async16(&sA[row * LD + l_q * 8], Ag + (size_t)row * K + k0 + l_q * 8);
            cp_async16(&sB[row * LD + l_q * 8], Bg + (size_t)row * K + k0 + l_q * 8);
        }
    };

    const int KT = K / BK;
    #pragma unroll
    for (int s = 0; s < GEMM_STAGES - 1; ++s) { load_stage(s, s); cp_commit(); }

    // lane-relative fragment addresses
    const int a_row = wm * 64 + (lane & 15);
    const int a_col = (lane >> 4) * 8;
    const int b_quad = lane >> 3;
    const int b_row = wn * 32 + (b_quad >> 1) * 8 + (lane & 7);
    const int b_col = (b_quad & 1) * 8;

    for (int kt = 0; kt < KT; ++kt) {
        cp_wait<GEMM_STAGES - 2>();
        __syncthreads();
        if (kt + GEMM_STAGES - 1 < KT) load_stage(kt + GEMM_STAGES - 1, (kt + GEMM_STAGES - 1) % GEMM_STAGES);
        cp_commit();

        const __nv_bfloat16* sA = smem + (size_t)(kt % GEMM_STAGES) * GEMM_STG;
        const __nv_bfloat16* sB = sA + BM * LD;

        #pragma unroll
        for (int kk = 0; kk < 2; ++kk) {
            const int kb = kk * 16;
            uint32_t afr[4][4], bfr[4][2];
            #pragma unroll
            for (int mi = 0; mi < 4; mi++)
                ldsm_x4(afr[mi], sA + (a_row + mi * 16) * LD + kb + a_col);
            #pragma unroll
            for (int p = 0; p < 2; p++) {
                uint32_t t[4];
                ldsm_x4(t, sB + (b_row + p * 16) * LD + kb + b_col);
                bfr[2 * p][0] = t[0]; bfr[2 * p][1] = t[1];
                bfr[2 * p + 1][0] = t[2]; bfr[2 * p + 1][1] = t[3];
            }
            #pragma unroll
            for (int mi = 0; mi < 4; mi++)
                #pragma unroll
                for (int ni = 0; ni < 4; ni++)
                    mma16816(acc[mi][ni], afr[mi], bfr[ni]);
        }
    }

    const int gid = lane >> 2, tig = lane & 3;
    #pragma unroll
    for (int mi = 0; mi < 4; mi++) {
        int row = m0 + wm * 64 + mi * 16 + gid;
        #pragma unroll
        for (int ni = 0; ni < 4; ni++) {
            int col = n0 + wn * 32 + ni * 8 + tig * 2;
            epi(row,     col, acc[mi][ni][0], acc[mi][ni][1]);
            epi(row + 8, col, acc[mi][ni][2], acc[mi][ni][3]);
        }
    }
}

// ---------------------------------------------------------------------------
// K3: per-token 12x12 attention (one warp per token)
// ---------------------------------------------------------------------------
__global__ void __launch_bounds__(128) attn_kernel(
    const __nv_bfloat16* __restrict__ qkv, __nv_bfloat16* __restrict__ a)
{
    __shared__ float s[4][3 * 396 + 144];
    const int wid = threadIdx.x >> 5, lane = threadIdx.x & 31;
    const int n = blockIdx.x * 4 + wid;

    float* sq = s[wid];
    float* sk = sq + 396;
    float* sv = sk + 396;
    float* sc = sv + 396;

    const __nv_bfloat16* src = qkv + (size_t)n * k3C;
    for (int i = lane; i < 144; i += 32) {           // 144 x 16B = 1152 bf16
        uint4 v = *(const uint4*)(src + 8 * i);
        int e = 8 * i;
        int sec = e / 384, rr = (e % 384) / 32, d = e % 32;
        float* dst = sq + sec * 396 + rr * 33 + d;
        __nv_bfloat162 p0 = *(__nv_bfloat162*)&v.x;
        __nv_bfloat162 p1 = *(__nv_bfloat162*)&v.y;
        __nv_bfloat162 p2 = *(__nv_bfloat162*)&v.z;
        __nv_bfloat162 p3 = *(__nv_bfloat162*)&v.w;
        dst[0] = __bfloat162float(p0.x); dst[1] = __bfloat162float(p0.y);
        dst[2] = __bfloat162float(p1.x); dst[3] = __bfloat162float(p1.y);
        dst[4] = __bfloat162float(p2.x); dst[5] = __bfloat162float(p2.y);
        dst[6] = __bfloat162float(p3.x); dst[7] = __bfloat162float(p3.y);
    }
    __syncwarp();

    const float scale = 0.17677669529663687f;
    for (int p = lane; p < 144; p += 32) {
        int i = p / 12, j = p % 12;
        float acc = 0.f;
        #pragma unroll
        for (int d = 0; d < 32; d++) acc += sq[i * 33 + d] * sk[j * 33 + d];
        sc[p] = acc * scale;
    }
    __syncwarp();

    if (lane < 12) {
        float mx = -1e30f;
        #pragma unroll
        for (int j = 0; j < 12; j++) mx = fmaxf(mx, sc[lane * 12 + j]);
        float e[12], sum = 0.f;
        #pragma unroll
        for (int j = 0; j < 12; j++) { e[j] = expf(sc[lane * 12 + j] - mx); sum += e[j]; }
        float inv = 1.f / sum;
        #pragma unroll
        for (int j = 0; j < 12; j++) sc[lane * 12 + j] = e[j] * inv;
    }
    __syncwarp();

    const int d = lane;
    __nv_bfloat16* dst = a + (size_t)n * kC + d * 12;
    #pragma unroll
    for (int i = 0; i < 12; i++) {
        float acc = 0.f;
        #pragma unroll
        for (int j = 0; j < 12; j++) acc += sc[i * 12 + j] * sv[j * 33 + d];
        dst[i] = __float2bfloat16(acc);
    }
}

// ---------------------------------------------------------------------------
// K8: out[b,c,nl] = x + gamma1*a + gamma2*m, transposed back (smem tiles)
// ---------------------------------------------------------------------------
#define OUT_SMEM (2 * 64 * 386 * 2)
__global__ void __launch_bounds__(256) out_kernel(
    const float* __restrict__ x,
    const __nv_bfloat16* __restrict__ a, const __nv_bfloat16* __restrict__ m,
    const float* __restrict__ gamma1, const float* __restrict__ gamma2,
    float* __restrict__ out)
{
    extern __shared__ __nv_bfloat16 sh[];
    __nv_bfloat16* sa = sh;
    __nv_bfloat16* sm = sh + 64 * 386;
    const int tid = threadIdx.x;
    const int blk = blockIdx.x;
    const int b   = blk / (kDHW / 64);
    const int nl0 = (blk % (kDHW / 64)) * 64;
    const size_t n0 = (size_t)b * kDHW + nl0;

    for (int idx = tid; idx < 64 * 192; idx += 256) {
        int t = idx / 192, cc = idx % 192;
        __nv_bfloat162 va = *(const __nv_bfloat162*)(a + (n0 + t) * kC + cc * 2);
        __nv_bfloat162 vm = *(const __nv_bfloat162*)(m + (n0 + t) * kC + cc * 2);
        sa[t * 386 + cc * 2]     = va.x;
        sa[t * 386 + cc * 2 + 1] = va.y;
        sm[t * 386 + cc * 2]     = vm.x;
        sm[t * 386 + cc * 2 + 1] = vm.y;
    }
    __syncthreads();

    const int tok  = tid & 63;
    const int csub = tid >> 6;
    for (int c = csub; c < kC; c += 4) {
        float av = __bfloat162float(sa[tok * 386 + c]);
        float mv = __bfloat162float(sm[tok * 386 + c]);
        size_t off = (size_t)b * kC * kDHW + (size_t)c * kDHW + nl0 + tok;
        out[off] = x[off] + gamma1[c] * av + gamma2[c] * mv;
    }
}

// ---------------------------------------------------------------------------
// Host launch
// ---------------------------------------------------------------------------
extern "C" void kernel_launch(void* const* d_in, const int* in_sizes, int n_in,
                              void* d_out, int out_size)
{
    (void)in_sizes; (void)n_in; (void)out_size;
    const float* x        = (const float*)d_in[0];
    const float* ln1_g    = (const float*)d_in[1];
    const float* ln1_b    = (const float*)d_in[2];
    const float* ln2_g    = (const float*)d_in[3];
    const float* ln2_b    = (const float*)d_in[4];
    const float* w_qkv    = (const float*)d_in[5];
    const float* b_qkv    = (const float*)d_in[6];
    const float* gamma1   = (const float*)d_in[7];
    const float* gamma2   = (const float*)d_in[8];
    const float* embed_w  = (const float*)d_in[9];
    const float* embed_b  = (const float*)d_in[10];
    const float* aff1_g   = (const float*)d_in[11];
    const float* aff1_b   = (const float*)d_in[12];
    const float* tok_w    = (const float*)d_in[13];
    const float* tok_b    = (const float*)d_in[14];
    const float* ls_a     = (const float*)d_in[15];
    const float* aff2_g   = (const float*)d_in[16];
    const float* aff2_b   = (const float*)d_in[17];
    const float* fc1_w    = (const float*)d_in[18];
    const float* fc1_b    = (const float*)d_in[19];
    const float* fc2_w    = (const float*)d_in[20];
    const float* fc2_b    = (const float*)d_in[21];
    const float* ls_b     = (const float*)d_in[22];
    const float* affout_g = (const float*)d_in[23];
    const float* affout_b = (const float*)d_in[24];
    const float* head_w   = (const float*)d_in[25];
    const float* head_b   = (const float*)d_in[26];
    float* out = (float*)d_out;

    __nv_bfloat16 *z, *qkv, *a, *u, *h, *v, *m;
    __nv_bfloat16 *wqe, *w1f, *w2, *whf;
    float *bqe, *b1f, *bhf;
    cudaGetSymbolAddress((void**)&z,   g_z);
    cudaGetSymbolAddress((void**)&qkv, g_qkv);
    cudaGetSymbolAddress((void**)&a,   g_a);
    cudaGetSymbolAddress((void**)&u,   g_u);
    cudaGetSymbolAddress((void**)&h,   g_h);
    cudaGetSymbolAddress((void**)&v,   g_v);
    cudaGetSymbolAddress((void**)&m,   g_m);
    cudaGetSymbolAddress((void**)&wqe, g_wqe);
    cudaGetSymbolAddress((void**)&w1f, g_w1f);
    cudaGetSymbolAddress((void**)&w2,  g_w2);
    cudaGetSymbolAddress((void**)&whf, g_whf);
    cudaGetSymbolAddress((void**)&bqe, g_bqe);
    cudaGetSymbolAddress((void**)&b1f, g_b1f);
    cudaGetSymbolAddress((void**)&bhf, g_bhf);

    cudaFuncSetAttribute(ln_transpose_kernel, cudaFuncAttributeMaxDynamicSharedMemorySize, LN_SMEM);
    cudaFuncSetAttribute(out_kernel,          cudaFuncAttributeMaxDynamicSharedMemorySize, OUT_SMEM);
    cudaFuncSetAttribute(gemm_kernel<EpiQkvEmbed>, cudaFuncAttributeMaxDynamicSharedMemorySize, GEMM_SMEM);
    cudaFuncSetAttribute(gemm_kernel<EpiGelu>,     cudaFuncAttributeMaxDynamicSharedMemorySize, GEMM_SMEM);
    cudaFuncSetAttribute(gemm_kernel<EpiFc2>,      cudaFuncAttributeMaxDynamicSharedMemorySize, GEMM_SMEM);
    cudaFuncSetAttribute(gemm_kernel<EpiBias>,     cudaFuncAttributeMaxDynamicSharedMemorySize, GEMM_SMEM);

    // K0: weight folding / conversion
    fold_kernel<<<k3C/4, 128>>>(w_qkv,   b_qkv,   ln1_g,    ln1_b,    wqe,             bqe,        k3C,  kC);
    fold_kernel<<<kC/4,  128>>>(embed_w, embed_b, ln2_g,    ln2_b,    wqe + k3C*kC,    bqe + k3C,  kC,   kC);
    fold_kernel<<<kHid/4,128>>>(fc1_w,   fc1_b,   aff2_g,   aff2_b,   w1f,             b1f,        kHid, kC);
    fold_kernel<<<kC/4,  128>>>(head_w,  head_b,  affout_g, affout_b, whf,             bhf,        kC,   kC);
    cvt_kernel<<<(kC*kHid + 255)/256, 256>>>(fc2_w, w2, kC*kHid);

    // K1: transpose + LN (affine folded into weights)
    ln_transpose_kernel<<<kN/64, 256, LN_SMEM>>>(x, z);

    // G1: merged qkv+embed:  [N,1536] = z @ [Wqkv'; We']^T
    gemm_kernel<<<dim3(kQE/128, kN/128), 256, GEMM_SMEM>>>(z, wqe, kN, kQE, kC,
        EpiQkvEmbed{bqe, qkv, ls_a, aff1_g, aff1_b, tok_w, tok_b, u});

    // K3: per-token attention
    attn_kernel<<<kN/4, 128>>>(qkv, a);

    // G2: fc1 + exact gelu (aff2 folded)
    gemm_kernel<<<dim3(kHid/128, kN/128), 256, GEMM_SMEM>>>(u, w1f, kN, kHid, kC,
        EpiGelu{b1f, h});

    // G3: fc2 + residual(u)
    gemm_kernel<<<dim3(kC/128, kN/128), 256, GEMM_SMEM>>>(h, w2, kN, kC, kHid,
        EpiFc2{fc2_b, ls_b, u, v});

    // G4: head (affout folded)
    gemm_kernel<<<dim3(kC/128, kN/128), 256, GEMM_SMEM>>>(v, whf, kN, kC, kC,
        EpiBias{bhf, m, kC});

    // K8: residual + transpose back
    out_kernel<<<kN/64, 256, OUT_SMEM>>>(x, a, m, gamma1, gamma2, out);
}